// round 12
// baseline (speedup 1.0000x reference)
#include <cuda_runtime.h>
#include <math.h>

constexpr int kT=1024, kH=2048, kNH=16, kNKV=4, kHD=128, kE=8, kI=768;
constexpr int kQKV = kNH*kHD + 2*kNKV*kHD;
constexpr float kEPS=1e-6f, kScale=0.08838834764831845f;
constexpr int kSlots=3072, kTiles=kSlots/128, kStages=3;

__device__ float g_h1[kT*kH];
__device__ float g_qkv[kT*kQKV];
__device__ float g_part[2*kT*kQKV];
__device__ float g_scores[(size_t)kNH*kT*kT];
__device__ float g_attn[kT*kH];
__device__ float g_h2[(kT+1)*kH];
__device__ float g_h2f[kT*kH];
__device__ float g_gu[(size_t)kSlots*2*kI];
__device__ float g_act[(size_t)kSlots*kI];
__device__ float g_ds[(size_t)kSlots*kH];
__device__ int   g_tok[kSlots];
__device__ float g_wt[kSlots];
__device__ int   g_slot_of[kT*2];
__device__ int   g_topi[kT*2];
__device__ float g_topw[kT*2];
__device__ int   g_cnt[kE];
__device__ int   g_cursor[kE];
__device__ int   g_tile_e[kTiles];
__device__ int   g_ntiles;

__device__ __forceinline__ unsigned f2tf(float x){unsigned r;asm("cvt.rna.tf32.f32 %0, %1;":"=r"(r):"f"(x));return r;}
__device__ __forceinline__ float rtf(float x){return __uint_as_float(f2tf(x));}
__device__ __forceinline__ void mma_tf32(float c[4],unsigned a0,unsigned a1,unsigned a2,unsigned a3,unsigned b0,unsigned b1){
    asm volatile("mma.sync.aligned.m16n8k8.row.col.f32.tf32.tf32.f32 {%0,%1,%2,%3}, {%4,%5,%6,%7}, {%8,%9}, {%0,%1,%2,%3};"
                 :"+f"(c[0]),"+f"(c[1]),"+f"(c[2]),"+f"(c[3]):"r"(a0),"r"(a1),"r"(a2),"r"(a3),"r"(b0),"r"(b1));
}
__device__ __forceinline__ unsigned sptr(const void* p){return (unsigned)__cvta_generic_to_shared(p);}
__device__ __forceinline__ void cp16(unsigned d,const void* s){asm volatile("cp.async.cg.shared.global [%0], [%1], 16;"::"r"(d),"l"(s));}
__device__ __forceinline__ void cp_commit(){asm volatile("cp.async.commit_group;");}
__device__ __forceinline__ void cp_wait1(){asm volatile("cp.async.wait_group 1;");}
__device__ __forceinline__ void ldsm4(unsigned&r0,unsigned&r1,unsigned&r2,unsigned&r3,unsigned a){
    asm volatile("ldmatrix.sync.aligned.m8n8.x4.shared.b16 {%0,%1,%2,%3}, [%4];":"=r"(r0),"=r"(r1),"=r"(r2),"=r"(r3):"r"(a));
}

constexpr int kSA=36, kSB=136, kABuf=128*kSA, kBBuf=32*kSB;
constexpr size_t kPlainSmem=(size_t)kStages*(kABuf+kBBuf)*4;
constexpr size_t kTTSmem=(size_t)kStages*2*kABuf*4;

__device__ __forceinline__ unsigned a_off(int wm,int lane){
    int sub=lane>>3, lr=lane&7;
    return 4u*((wm+(sub&1)*8+lr)*kSA + (sub>>1)*4);
}
__device__ __forceinline__ unsigned b_off(int wn,int p,int lane){
    int sub=lane>>3, lr=lane&7;
    return 4u*((wn+p*16+(sub>>1)*8+lr)*kSA + (sub&1)*4);
}
// 32x32 warp tile: 2 m16 x 4 n8 = 8 MMA per k8
template <bool DoCvt>
__device__ __forceinline__ void compute_plain(unsigned aB,const unsigned* __restrict__ Bc,int wn,int g,int t,float acc[2][4][4]){
    #pragma unroll
    for (int kk = 0; kk < 32; kk += 8) {
        unsigned a[2][4], b[4][2];
        ldsm4(a[0][0],a[0][1],a[0][2],a[0][3], aB+4u*kk);
        ldsm4(a[1][0],a[1][1],a[1][2],a[1][3], aB+4u*(16*kSA+kk));
        #pragma unroll
        for (int jn = 0; jn < 4; jn++) {
            unsigned b0 = Bc[(kk+t)*kSB+wn+jn*8+g];
            unsigned b1 = Bc[(kk+t+4)*kSB+wn+jn*8+g];
            if (DoCvt) { b[jn][0]=f2tf(__uint_as_float(b0)); b[jn][1]=f2tf(__uint_as_float(b1)); }
            else       { b[jn][0]=b0; b[jn][1]=b1; }
        }
        #pragma unroll
        for (int im = 0; im < 2; im++)
            #pragma unroll
            for (int jn = 0; jn < 4; jn++)
                mma_tf32(acc[im][jn],a[im][0],a[im][1],a[im][2],a[im][3],b[jn][0],b[jn][1]);
    }
}
__device__ __forceinline__ void compute_tt(unsigned aB,unsigned b0a,unsigned b1a,float acc[2][4][4]){
    #pragma unroll
    for (int kk = 0; kk < 32; kk += 8) {
        unsigned a[2][4], b[4][2];
        ldsm4(a[0][0],a[0][1],a[0][2],a[0][3], aB+4u*kk);
        ldsm4(a[1][0],a[1][1],a[1][2],a[1][3], aB+4u*(16*kSA+kk));
        ldsm4(b[0][0],b[0][1],b[1][0],b[1][1], b0a+4u*kk);
        ldsm4(b[2][0],b[2][1],b[3][0],b[3][1], b1a+4u*kk);
        #pragma unroll
        for (int im = 0; im < 2; im++)
            #pragma unroll
            for (int jn = 0; jn < 4; jn++)
                mma_tf32(acc[im][jn],a[im][0],a[im][1],a[im][2],a[im][3],b[jn][0],b[jn][1]);
    }
}

__global__ void add_rms_kernel(const float* __restrict__ x,const float* __restrict__ r,
                               const float* __restrict__ w,float* __restrict__ res_out,
                               float* __restrict__ h_out,float* __restrict__ h_full){
    const int t = blockIdx.x, tid = threadIdx.x;
    const float* xp = x + (size_t)t*kH;
    const float* rp = r ? r + (size_t)t*kH : nullptr;
    float v[8]; float ss = 0.f;
    #pragma unroll
    for (int i = 0; i < 8; i++) {
        int idx = tid + i*256;
        float val = xp[idx];
        if (rp) val += rp[idx];
        v[i] = val; ss += val*val;
    }
    __shared__ float sh[256];
    sh[tid] = ss; __syncthreads();
    for (int s = 128; s > 0; s >>= 1) { if (tid < s) sh[tid] += sh[tid+s]; __syncthreads(); }
    float scale = rsqrtf(sh[0]/(float)kH + kEPS);
    #pragma unroll
    for (int i = 0; i < 8; i++) {
        int idx = tid + i*256;
        if (res_out) res_out[(size_t)t*kH + idx] = v[i];
        float hv = v[i]*scale*w[idx];
        h_out[(size_t)t*kH + idx] = rtf(hv);
        if (h_full) h_full[(size_t)t*kH + idx] = hv;
    }
}

// ---------------- split-K 128x128 GEMM, 512 threads ----------------
__global__ void __launch_bounds__(512, 2)
gemm_splitk_kernel(const float* __restrict__ A,int lda,const float* __restrict__ B,int ldb,
                   float* __restrict__ Cpart,int ldc,int Kdim){
    extern __shared__ unsigned smem[];
    unsigned* As = smem;
    unsigned* Bs = smem + kStages*kABuf;
    const int row0 = blockIdx.x*128, col0 = blockIdx.y*128;
    const int kz = blockIdx.z;
    const int Khalf = Kdim >> 1;
    const int koff = kz*Khalf;
    const int tid = threadIdx.x, lane = tid&31, warp = tid>>5;
    const int wm = (warp&3)*32, wn = (warp>>2)*32;
    const int g = lane>>2, t = lane&3;
    const float* Ab = A + (size_t)row0*lda + koff;
    const float* Bb = B + (size_t)koff*ldb + col0;
    float* C = Cpart + (size_t)kz*kT*ldc;
    const int nk = Khalf >> 5;

    auto issue = [&](int s){
        unsigned* Ad = As + (s%kStages)*kABuf;
        unsigned* Bd = Bs + (s%kStages)*kBBuf;
        int kk0 = s*32;
        #pragma unroll
        for (int q = 0; q < 2; q++) {
            int e = tid + q*512;
            int m = e>>3, k4 = e&7;
            cp16(sptr(Ad + m*kSA + k4*4), Ab + (size_t)m*lda + kk0 + k4*4);
        }
        #pragma unroll
        for (int q = 0; q < 2; q++) {
            int e = tid + q*512;
            int k = e>>5, n16 = e&31;
            cp16(sptr(Bd + k*kSB + n16*4), Bb + (size_t)(kk0+k)*ldb + n16*4);
        }
        cp_commit();
    };
    for (int s = 0; s < kStages-1; s++) { if (s < nk) issue(s); else cp_commit(); }

    const unsigned aO = a_off(wm,lane);
    float acc[2][4][4] = {};
    for (int i = 0; i < nk; i++) {
        cp_wait1();
        __syncthreads();
        int s = i + kStages - 1;
        if (s < nk) issue(s); else cp_commit();
        compute_plain<true>(sptr(As + (i%kStages)*kABuf) + aO, Bs + (i%kStages)*kBBuf, wn, g, t, acc);
    }
    #pragma unroll
    for (int im = 0; im < 2; im++)
        #pragma unroll
        for (int jn = 0; jn < 4; jn++) {
            int r0 = row0 + wm + im*16 + g;
            int c0 = col0 + wn + jn*8 + 2*t;
            #pragma unroll
            for (int hh = 0; hh < 2; hh++) {
                int rr = r0 + hh*8;
                C[(size_t)rr*ldc + c0]   = acc[im][jn][hh*2+0];
                C[(size_t)rr*ldc + c0+1] = acc[im][jn][hh*2+1];
            }
        }
}

__global__ void reduce_kernel(const float* __restrict__ p0,const float* __restrict__ p1,
                              const float* __restrict__ addsrc,float* __restrict__ out,int n4){
    int i = blockIdx.x*256 + threadIdx.x;
    if (i >= n4) return;
    float4 a = reinterpret_cast<const float4*>(p0)[i];
    float4 b = reinterpret_cast<const float4*>(p1)[i];
    float4 v = make_float4(a.x+b.x, a.y+b.y, a.z+b.z, a.w+b.w);
    if (addsrc) {
        float4 c = reinterpret_cast<const float4*>(addsrc)[i];
        v.x += c.x; v.y += c.y; v.z += c.z; v.w += c.w;
    }
    reinterpret_cast<float4*>(out)[i] = v;
}

__global__ void rope_kernel(const int* __restrict__ positions,const float* __restrict__ q_norm_w,
                            const float* __restrict__ k_norm_w){
    const int t = blockIdx.x, hh = blockIdx.y, lane = threadIdx.x;
    if (hh >= kNH + kNKV) {
        int vh = hh - kNH - kNKV;
        float* ptr = g_qkv + (size_t)t*kQKV + (kNH+kNKV)*kHD + vh*kHD;
        ptr[lane] = rtf(ptr[lane]);
        return;
    }
    float* ptr = g_qkv + (size_t)t*kQKV + (hh < kNH ? hh*kHD : kNH*kHD + (hh-kNH)*kHD);
    const float* nw = (hh < kNH) ? q_norm_w : k_norm_w;
    float v = ptr[lane];
    __shared__ float sred[128];
    sred[lane] = v*v; __syncthreads();
    for (int s = 64; s > 0; s >>= 1) { if (lane < s) sred[lane] += sred[lane+s]; __syncthreads(); }
    float scale = rsqrtf(sred[0]/(float)kHD + kEPS);
    float xn = v*scale*nw[lane];
    __shared__ float sh[128];
    sh[lane] = xn; __syncthreads();
    int j = lane & 63;
    const float kLog2Theta_64 = 19.931568569324174f / 64.0f;
    float inv = exp2f(-(float)j * kLog2Theta_64);
    float ang = (float)positions[t] * inv;
    float s, c;
    sincosf(ang, &s, &c);
    float outv = (lane < 64) ? sh[lane]*c - sh[lane+64]*s : sh[lane]*c + sh[lane-64]*s;
    ptr[lane] = rtf(outv);
}

__global__ void __launch_bounds__(512,2) scores_kernel(){
    const int qt = blockIdx.x, kt = blockIdx.y, h = blockIdx.z;
    if (kt > qt) return;
    extern __shared__ unsigned smw[];
    unsigned* As = smw;
    unsigned* Bst = smw + kStages*kABuf;
    const float* Q  = g_qkv + (size_t)qt*128*kQKV + h*kHD;
    const float* Kp = g_qkv + (size_t)kt*128*kQKV + kNH*kHD + (h>>2)*kHD;
    const int tid = threadIdx.x, lane = tid&31, warp = tid>>5;
    const int wm = (warp&3)*32, wn = (warp>>2)*32;
    const int g = lane>>2, t = lane&3;
    const int nk = kHD >> 5;
    auto issue = [&](int s){
        unsigned* Ad = As + (s%kStages)*kABuf;
        unsigned* Bd = Bst + (s%kStages)*kABuf;
        int kk0 = s*32;
        #pragma unroll
        for (int q = 0; q < 2; q++) {
            int e = tid + q*512;
            int m = e>>3, k4 = e&7;
            cp16(sptr(Ad + m*kSA + k4*4), Q  + (size_t)m*kQKV + kk0 + k4*4);
            cp16(sptr(Bd + m*kSA + k4*4), Kp + (size_t)m*kQKV + kk0 + k4*4);
        }
        cp_commit();
    };
    for (int s = 0; s < kStages-1; s++) { if (s < nk) issue(s); else cp_commit(); }
    const unsigned aO = a_off(wm,lane), b0 = b_off(wn,0,lane), b1 = b_off(wn,1,lane);
    float acc[2][4][4] = {};
    for (int i = 0; i < nk; i++) {
        cp_wait1();
        __syncthreads();
        int s = i + kStages - 1;
        if (s < nk) issue(s); else cp_commit();
        int p = i % kStages;
        compute_tt(sptr(As+p*kABuf)+aO, sptr(Bst+p*kABuf)+b0, sptr(Bst+p*kABuf)+b1, acc);
    }
    const int row0 = qt*128, col0 = kt*128;
    #pragma unroll
    for (int im = 0; im < 2; im++)
        #pragma unroll
        for (int jn = 0; jn < 4; jn++) {
            int r0 = row0 + wm + im*16 + g;
            int c0 = col0 + wn + jn*8 + 2*t;
            #pragma unroll
            for (int hh = 0; hh < 2; hh++) {
                int qi = r0 + hh*8;
                float v0 = acc[im][jn][hh*2+0]*kScale;
                float v1 = acc[im][jn][hh*2+1]*kScale;
                if (c0   > qi) v0 = -1e9f;
                if (c0+1 > qi) v1 = -1e9f;
                g_scores[((size_t)h*kT+qi)*kT + c0]   = v0;
                g_scores[((size_t)h*kT+qi)*kT + c0+1] = v1;
            }
        }
}

__global__ void softmax_kernel(){
    const int q = blockIdx.x, h = blockIdx.y, tid = threadIdx.x;
    float* row = g_scores + ((size_t)h*kT + q)*kT;
    const int tend = ((q>>7)+1)<<7;
    __shared__ float sh[256];
    float lmax = -3.4e38f;
    for (int k = tid; k <= q; k += 256) lmax = fmaxf(lmax, row[k]);
    sh[tid] = lmax; __syncthreads();
    for (int s = 128; s > 0; s >>= 1) { if (tid < s) sh[tid] = fmaxf(sh[tid], sh[tid+s]); __syncthreads(); }
    float m = sh[0]; __syncthreads();
    float lsum = 0.f;
    for (int k = tid; k <= q; k += 256) { float e = __expf(row[k]-m); row[k] = e; lsum += e; }
    sh[tid] = lsum; __syncthreads();
    for (int s = 128; s > 0; s >>= 1) { if (tid < s) sh[tid] += sh[tid+s]; __syncthreads(); }
    float inv = 1.f/sh[0];
    for (int k = tid; k < tend; k += 256) row[k] = (k <= q) ? rtf(row[k]*inv) : 0.f;
}

__global__ void __launch_bounds__(512,2) pv_kernel(){
    const int qt = blockIdx.x, h = blockIdx.y;
    extern __shared__ unsigned smw[];
    unsigned* As = smw;
    unsigned* Bs = smw + kStages*kABuf;
    const int row0 = qt*128;
    const int Kdim = (qt+1)*128;
    const float* A = g_scores + ((size_t)h*kT + row0)*kT;
    const float* B = g_qkv + (kNH+kNKV)*kHD + (h>>2)*kHD;
    const int tid = threadIdx.x, lane = tid&31, warp = tid>>5;
    const int wm = (warp&3)*32, wn = (warp>>2)*32;
    const int g = lane>>2, t = lane&3;
    const int nk = Kdim >> 5;
    auto issue = [&](int s){
        unsigned* Ad = As + (s%kStages)*kABuf;
        unsigned* Bd = Bs + (s%kStages)*kBBuf;
        int kk0 = s*32;
        #pragma unroll
        for (int q = 0; q < 2; q++) {
            int e = tid + q*512;
            int m = e>>3, k4 = e&7;
            cp16(sptr(Ad + m*kSA + k4*4), A + (size_t)m*kT + kk0 + k4*4);
        }
        #pragma unroll
        for (int q = 0; q < 2; q++) {
            int e = tid + q*512;
            int k = e>>5, n16 = e&31;
            cp16(sptr(Bd + k*kSB + n16*4), B + (size_t)(kk0+k)*kQKV + n16*4);
        }
        cp_commit();
    };
    for (int s = 0; s < kStages-1; s++) { if (s < nk) issue(s); else cp_commit(); }
    const unsigned aO = a_off(wm,lane);
    float acc[2][4][4] = {};
    for (int i = 0; i < nk; i++) {
        cp_wait1();
        __syncthreads();
        int s = i + kStages - 1;
        if (s < nk) issue(s); else cp_commit();
        int p = i % kStages;
        compute_plain<false>(sptr(As+p*kABuf)+aO, Bs+p*kBBuf, wn, g, t, acc);
    }
    #pragma unroll
    for (int im = 0; im < 2; im++)
        #pragma unroll
        for (int jn = 0; jn < 4; jn++) {
            int r0 = row0 + wm + im*16 + g;
            int c0 = wn + jn*8 + 2*t;
            #pragma unroll
            for (int hh = 0; hh < 2; hh++) {
                int rr = r0 + hh*8;
                g_attn[(size_t)rr*kH + h*kHD + c0]   = rtf(acc[im][jn][hh*2+0]);
                g_attn[(size_t)rr*kH + h*kHD + c0+1] = rtf(acc[im][jn][hh*2+1]);
            }
        }
}

__global__ void router_kernel(const float* __restrict__ gate_w){
    const int t = blockIdx.x, tid = threadIdx.x;
    const float* hp = g_h2f + (size_t)t*kH;
    float acc[kE] = {};
    for (int k = tid; k < kH; k += 256) {
        float hv = hp[k];
        const float* gw = gate_w + (size_t)k*kE;
        #pragma unroll
        for (int e = 0; e < kE; e++) acc[e] += hv*gw[e];
    }
    __shared__ float sh[kE][256];
    #pragma unroll
    for (int e = 0; e < kE; e++) sh[e][tid] = acc[e];
    __syncthreads();
    for (int s = 128; s > 0; s >>= 1) {
        if (tid < s) {
            #pragma unroll
            for (int e = 0; e < kE; e++) sh[e][tid] += sh[e][tid+s];
        }
        __syncthreads();
    }
    if (tid == 0) {
        float l[kE], mx = -3.4e38f;
        #pragma unroll
        for (int e = 0; e < kE; e++) { l[e] = sh[e][0]; mx = fmaxf(mx, l[e]); }
        float sum = 0.f;
        #pragma unroll
        for (int e = 0; e < kE; e++) { l[e] = __expf(l[e]-mx); sum += l[e]; }
        float isum = 1.f/sum;
        float best = -1.f, second = -1.f; int bi = 0, si = 0;
        #pragma unroll
        for (int e = 0; e < kE; e++) {
            float p = l[e]*isum;
            if (p > best) { second = best; si = bi; best = p; bi = e; }
            else if (p > second) { second = p; si = e; }
        }
        float denom = 1.f/(best + second);
        g_topi[t*2]   = bi; g_topw[t*2]   = best*denom;
        g_topi[t*2+1] = si; g_topw[t*2+1] = second*denom;
        atomicAdd(&g_cnt[bi], 1);
        atomicAdd(&g_cnt[si], 1);
    }
}

__global__ void moe_init_kernel(){
    int i = blockIdx.x*256 + threadIdx.x;
    if (i < kE) g_cnt[i] = 0;
    if (i < kSlots) g_tok[i] = kT;
    if (i < kH) g_h2[(size_t)kT*kH + i] = 0.f;
}
__global__ void moe_setup_kernel(){
    int off = 0, tile = 0;
    for (int e = 0; e < kE; e++) {
        g_cursor[e] = off;
        int seg = ((g_cnt[e] + 127)/128)*128;
        for (int i = 0; i < seg/128; i++) g_tile_e[tile++] = e;
        off += seg;
    }
    g_ntiles = tile;
}
__global__ void moe_scatter_kernel(){
    int t = blockIdx.x*256 + threadIdx.x;
    if (t >= kT) return;
    #pragma unroll
    for (int k = 0; k < 2; k++) {
        int e = g_topi[t*2+k];
        int pos = atomicAdd(&g_cursor[e], 1);
        g_tok[pos] = t;
        g_wt[pos]  = g_topw[t*2+k];
        g_slot_of[t*2+k] = pos;
    }
}

__global__ void __launch_bounds__(512,2) moe_gu_kernel(const float* __restrict__ w_gate_up){
    const int tile = blockIdx.x;
    if (tile >= g_ntiles) return;
    extern __shared__ unsigned smw[];
    unsigned* As = smw;
    unsigned* Bs = smw + kStages*kABuf;
    __shared__ int rows[128];
    const int tid = threadIdx.x;
    if (tid < 128) rows[tid] = g_tok[tile*128 + tid];
    __syncthreads();
    const int e = g_tile_e[tile];
    const int col0 = blockIdx.y*128;
    const float* Bb = w_gate_up + (size_t)e*kH*2*kI + col0;
    const int lane = tid&31, warp = tid>>5;
    const int wm = (warp&3)*32, wn = (warp>>2)*32;
    const int g = lane>>2, t = lane&3;
    const int nk = kH >> 5;
    auto issue = [&](int s){
        unsigned* Ad = As + (s%kStages)*kABuf;
        unsigned* Bd = Bs + (s%kStages)*kBBuf;
        int kk0 = s*32;
        #pragma unroll
        for (int q = 0; q < 2; q++) {
            int ee = tid + q*512;
            int m = ee>>3, k4 = ee&7;
            cp16(sptr(Ad + m*kSA + k4*4), g_h2 + (size_t)rows[m]*kH + kk0 + k4*4);
        }
        #pragma unroll
        for (int q = 0; q < 2; q++) {
            int ee = tid + q*512;
            int k = ee>>5, n16 = ee&31;
            cp16(sptr(Bd + k*kSB + n16*4), Bb + (size_t)(kk0+k)*(2*kI) + n16*4);
        }
        cp_commit();
    };
    for (int s = 0; s < kStages-1; s++) { if (s < nk) issue(s); else cp_commit(); }
    const unsigned aO = a_off(wm,lane);
    float acc[2][4][4] = {};
    for (int i = 0; i < nk; i++) {
        cp_wait1();
        __syncthreads();
        int s = i + kStages - 1;
        if (s < nk) issue(s); else cp_commit();
        int p = i % kStages;
        compute_plain<true>(sptr(As+p*kABuf)+aO, Bs+p*kBBuf, wn, g, t, acc);
    }
    #pragma unroll
    for (int im = 0; im < 2; im++)
        #pragma unroll
        for (int jn = 0; jn < 4; jn++) {
            int r0 = wm + im*16 + g;
            int c0 = col0 + wn + jn*8 + 2*t;
            #pragma unroll
            for (int hh = 0; hh < 2; hh++) {
                int slot = tile*128 + r0 + hh*8;
                g_gu[(size_t)slot*2*kI + c0]   = acc[im][jn][hh*2+0];
                g_gu[(size_t)slot*2*kI + c0+1] = acc[im][jn][hh*2+1];
            }
        }
}

__global__ void silu_kernel(){
    int idx = blockIdx.x*256 + threadIdx.x;
    int slot = idx / kI, j = idx % kI;
    if (slot >= g_ntiles*128) return;
    float g = g_gu[(size_t)slot*2*kI + j];
    float u = g_gu[(size_t)slot*2*kI + kI + j];
    g_act[idx] = rtf((g / (1.f + __expf(-g))) * u);
}

__global__ void __launch_bounds__(512,2) moe_down_kernel(const float* __restrict__ w_down){
    const int tile = blockIdx.x;
    if (tile >= g_ntiles) return;
    extern __shared__ unsigned smw[];
    unsigned* As = smw;
    unsigned* Bs = smw + kStages*kABuf;
    const int e = g_tile_e[tile];
    const int col0 = blockIdx.y*128;
    const float* A  = g_act + (size_t)tile*128*kI;
    const float* Bb = w_down + (size_t)e*kI*kH + col0;
    const int tid = threadIdx.x, lane = tid&31, warp = tid>>5;
    const int wm = (warp&3)*32, wn = (warp>>2)*32;
    const int g = lane>>2, t = lane&3;
    const int nk = kI >> 5;
    auto issue = [&](int s){
        unsigned* Ad = As + (s%kStages)*kABuf;
        unsigned* Bd = Bs + (s%kStages)*kBBuf;
        int kk0 = s*32;
        #pragma unroll
        for (int q = 0; q < 2; q++) {
            int ee = tid + q*512;
            int m = ee>>3, k4 = ee&7;
            cp16(sptr(Ad + m*kSA + k4*4), A + (size_t)m*kI + kk0 + k4*4);
        }
        #pragma unroll
        for (int q = 0; q < 2; q++) {
            int ee = tid + q*512;
            int k = ee>>5, n16 = ee&31;
            cp16(sptr(Bd + k*kSB + n16*4), Bb + (size_t)(kk0+k)*kH + n16*4);
        }
        cp_commit();
    };
    for (int s = 0; s < kStages-1; s++) { if (s < nk) issue(s); else cp_commit(); }
    const unsigned aO = a_off(wm,lane);
    float acc[2][4][4] = {};
    for (int i = 0; i < nk; i++) {
        cp_wait1();
        __syncthreads();
        int s = i + kStages - 1;
        if (s < nk) issue(s); else cp_commit();
        int p = i % kStages;
        compute_plain<true>(sptr(As+p*kABuf)+aO, Bs+p*kBBuf, wn, g, t, acc);
    }
    #pragma unroll
    for (int im = 0; im < 2; im++)
        #pragma unroll
        for (int jn = 0; jn < 4; jn++) {
            int r0 = wm + im*16 + g;
            int c0 = col0 + wn + jn*8 + 2*t;
            #pragma unroll
            for (int hh = 0; hh < 2; hh++) {
                int slot = tile*128 + r0 + hh*8;
                g_ds[(size_t)slot*kH + c0]   = acc[im][jn][hh*2+0];
                g_ds[(size_t)slot*kH + c0+1] = acc[im][jn][hh*2+1];
            }
        }
}

__global__ void combine_kernel(float* __restrict__ out){
    const int t = blockIdx.x;
    const int s0 = g_slot_of[t*2], s1 = g_slot_of[t*2+1];
    const float w0 = g_wt[s0], w1 = g_wt[s1];
    for (int j = threadIdx.x; j < kH; j += 256)
        out[(size_t)t*kH + j] = w0*g_ds[(size_t)s0*kH + j] + w1*g_ds[(size_t)s1*kH + j];
}

extern "C" void kernel_launch(void* const* d_in, const int* in_sizes, int n_in,
                              void* d_out, int out_size) {
    const int*   positions = (const int*)  d_in[0];
    const float* hidden    = (const float*)d_in[1];
    const float* residual  = (const float*)d_in[2];
    const float* w_qkv     = (const float*)d_in[3];
    const float* w_o       = (const float*)d_in[4];
    const float* q_norm_w  = (const float*)d_in[5];
    const float* k_norm_w  = (const float*)d_in[6];
    const float* ln1_w     = (const float*)d_in[7];
    const float* ln2_w     = (const float*)d_in[8];
    const float* gate_w    = (const float*)d_in[9];
    const float* w_gate_up = (const float*)d_in[10];
    const float* w_down    = (const float*)d_in[11];
    float* out = (float*)d_out;
    float* res = out + (size_t)kT*kH;

    float* d_h1;   cudaGetSymbolAddress((void**)&d_h1,  g_h1);
    float* d_qkv;  cudaGetSymbolAddress((void**)&d_qkv, g_qkv);
    float* d_part; cudaGetSymbolAddress((void**)&d_part,g_part);
    float* d_attn; cudaGetSymbolAddress((void**)&d_attn,g_attn);
    float* d_h2;   cudaGetSymbolAddress((void**)&d_h2,  g_h2);
    float* d_h2f;  cudaGetSymbolAddress((void**)&d_h2f, g_h2f);

    cudaFuncSetAttribute(gemm_splitk_kernel, cudaFuncAttributeMaxDynamicSharedMemorySize, (int)kPlainSmem);
    cudaFuncSetAttribute(scores_kernel,      cudaFuncAttributeMaxDynamicSharedMemorySize, (int)kTTSmem);
    cudaFuncSetAttribute(pv_kernel,          cudaFuncAttributeMaxDynamicSharedMemorySize, (int)kPlainSmem);
    cudaFuncSetAttribute(moe_gu_kernel,      cudaFuncAttributeMaxDynamicSharedMemorySize, (int)kPlainSmem);
    cudaFuncSetAttribute(moe_down_kernel,    cudaFuncAttributeMaxDynamicSharedMemorySize, (int)kPlainSmem);

    add_rms_kernel<<<kT, 256>>>(hidden, residual, ln1_w, res, d_h1, nullptr);
    gemm_splitk_kernel<<<dim3(kT/128, kQKV/128, 2), 512, kPlainSmem>>>(d_h1, kH, w_qkv, kQKV, d_part, kQKV, kH);
    reduce_kernel<<<(kT*kQKV/4 + 255)/256, 256>>>(d_part, d_part + (size_t)kT*kQKV, nullptr, d_qkv, kT*kQKV/4);
    rope_kernel<<<dim3(kT, kNH + 2*kNKV), 128>>>(positions, q_norm_w, k_norm_w);
    scores_kernel<<<dim3(kT/128, kT/128, kNH), 512, kTTSmem>>>();
    softmax_kernel<<<dim3(kT, kNH), 256>>>();
    pv_kernel<<<dim3(kT/128, kNH), 512, kPlainSmem>>>();
    gemm_splitk_kernel<<<dim3(kT/128, kH/128, 2), 512, kPlainSmem>>>(d_attn, kH, w_o, kH, d_part, kH, kH);
    reduce_kernel<<<(kT*kH/4 + 255)/256, 256>>>(d_part, d_part + (size_t)kT*kH, res, res, kT*kH/4);
    add_rms_kernel<<<kT, 256>>>(res, nullptr, ln2_w, nullptr, d_h2, d_h2f);
    moe_init_kernel<<<(kSlots + 255)/256, 256>>>();
    router_kernel<<<kT, 256>>>(gate_w);
    moe_setup_kernel<<<1, 1>>>();
    moe_scatter_kernel<<<(kT + 255)/256, 256>>>();
    moe_gu_kernel<<<dim3(kTiles, 2*kI/128), 512, kPlainSmem>>>(w_gate_up);
    silu_kernel<<<(kSlots*kI)/256, 256>>>();
    moe_down_kernel<<<dim3(kTiles, kH/128), 512, kPlainSmem>>>(w_down);
    combine_kernel<<<kT, 256>>>(out);
}

// round 13
// speedup vs baseline: 1.0633x; 1.0633x over previous
#include <cuda_runtime.h>
#include <math.h>

constexpr int kT=1024, kH=2048, kNH=16, kNKV=4, kHD=128, kE=8, kI=768;
constexpr int kQKV = kNH*kHD + 2*kNKV*kHD;
constexpr float kEPS=1e-6f, kScale=0.08838834764831845f;
constexpr int kSlots=3072, kTiles=kSlots/128, kStages=3;

__device__ float g_h1[kT*kH];
__device__ float g_qkv[kT*kQKV];
__device__ float g_part[2*kT*kQKV];
__device__ float g_scores[(size_t)kNH*kT*kT];
__device__ float g_attn[kT*kH];
__device__ float g_h2[(kT+1)*kH];
__device__ float g_h2f[kT*kH];
__device__ float g_gu[(size_t)kSlots*2*kI];
__device__ float g_act[(size_t)kSlots*kI];
__device__ float g_ds[(size_t)kSlots*kH];
__device__ int   g_tok[kSlots];
__device__ float g_wt[kSlots];
__device__ int   g_slot_of[kT*2];
__device__ int   g_topi[kT*2];
__device__ float g_topw[kT*2];
__device__ int   g_cnt[kE];
__device__ int   g_cursor[kE];
__device__ int   g_tile_e[kTiles];
__device__ int   g_ntiles;

__device__ __forceinline__ unsigned f2tf(float x){unsigned r;asm("cvt.rna.tf32.f32 %0, %1;":"=r"(r):"f"(x));return r;}
__device__ __forceinline__ float rtf(float x){return __uint_as_float(f2tf(x));}
__device__ __forceinline__ void mma_tf32(float c[4],unsigned a0,unsigned a1,unsigned a2,unsigned a3,unsigned b0,unsigned b1){
    asm volatile("mma.sync.aligned.m16n8k8.row.col.f32.tf32.tf32.f32 {%0,%1,%2,%3}, {%4,%5,%6,%7}, {%8,%9}, {%0,%1,%2,%3};"
                 :"+f"(c[0]),"+f"(c[1]),"+f"(c[2]),"+f"(c[3]):"r"(a0),"r"(a1),"r"(a2),"r"(a3),"r"(b0),"r"(b1));
}
__device__ __forceinline__ unsigned sptr(const void* p){return (unsigned)__cvta_generic_to_shared(p);}
__device__ __forceinline__ void cp16(unsigned d,const void* s){asm volatile("cp.async.cg.shared.global [%0], [%1], 16;"::"r"(d),"l"(s));}
__device__ __forceinline__ void cp_commit(){asm volatile("cp.async.commit_group;");}
__device__ __forceinline__ void cp_wait1(){asm volatile("cp.async.wait_group 1;");}
__device__ __forceinline__ void ldsm4(unsigned&r0,unsigned&r1,unsigned&r2,unsigned&r3,unsigned a){
    asm volatile("ldmatrix.sync.aligned.m8n8.x4.shared.b16 {%0,%1,%2,%3}, [%4];":"=r"(r0),"=r"(r1),"=r"(r2),"=r"(r3):"r"(a));
}

constexpr int kSA=36, kSB=136, kABuf=128*kSA, kBBuf=32*kSB;
constexpr size_t kPlainSmem=(size_t)kStages*(kABuf+kBBuf)*4;
constexpr size_t kTTSmem=(size_t)kStages*2*kABuf*4;

__device__ __forceinline__ unsigned a_off(int wm,int lane){
    int sub=lane>>3, lr=lane&7;
    return 4u*((wm+(sub&1)*8+lr)*kSA + (sub>>1)*4);
}
__device__ __forceinline__ unsigned b_off(int wn,int p,int lane){
    int sub=lane>>3, lr=lane&7;
    return 4u*((wn+p*16+(sub>>1)*8+lr)*kSA + (sub&1)*4);
}
template <bool DoCvt>
__device__ __forceinline__ void compute_plain(unsigned aB,const unsigned* __restrict__ Bc,int wn,int g,int t,float acc[4][4][4]){
    #pragma unroll
    for (int kk = 0; kk < 32; kk += 8) {
        unsigned a[4][4], b[4][2];
        #pragma unroll
        for (int im = 0; im < 4; im++) ldsm4(a[im][0],a[im][1],a[im][2],a[im][3], aB+4u*(im*16*kSA+kk));
        #pragma unroll
        for (int jn = 0; jn < 4; jn++) {
            unsigned b0 = Bc[(kk+t)*kSB+wn+jn*8+g];
            unsigned b1 = Bc[(kk+t+4)*kSB+wn+jn*8+g];
            if (DoCvt) { b[jn][0]=f2tf(__uint_as_float(b0)); b[jn][1]=f2tf(__uint_as_float(b1)); }
            else       { b[jn][0]=b0; b[jn][1]=b1; }
        }
        #pragma unroll
        for (int im = 0; im < 4; im++)
            #pragma unroll
            for (int jn = 0; jn < 4; jn++)
                mma_tf32(acc[im][jn],a[im][0],a[im][1],a[im][2],a[im][3],b[jn][0],b[jn][1]);
    }
}
__device__ __forceinline__ void compute_tt(unsigned aB,unsigned b0a,unsigned b1a,float acc[4][4][4]){
    #pragma unroll
    for (int kk = 0; kk < 32; kk += 8) {
        unsigned a[4][4], b[4][2];
        #pragma unroll
        for (int im = 0; im < 4; im++) ldsm4(a[im][0],a[im][1],a[im][2],a[im][3], aB+4u*(im*16*kSA+kk));
        ldsm4(b[0][0],b[0][1],b[1][0],b[1][1], b0a+4u*kk);
        ldsm4(b[2][0],b[2][1],b[3][0],b[3][1], b1a+4u*kk);
        #pragma unroll
        for (int im = 0; im < 4; im++)
            #pragma unroll
            for (int jn = 0; jn < 4; jn++)
                mma_tf32(acc[im][jn],a[im][0],a[im][1],a[im][2],a[im][3],b[jn][0],b[jn][1]);
    }
}

__global__ void add_rms_kernel(const float* __restrict__ x,const float* __restrict__ r,
                               const float* __restrict__ w,float* __restrict__ res_out,
                               float* __restrict__ h_out,float* __restrict__ h_full){
    const int t = blockIdx.x, tid = threadIdx.x;
    const float* xp = x + (size_t)t*kH;
    const float* rp = r ? r + (size_t)t*kH : nullptr;
    float v[8]; float ss = 0.f;
    #pragma unroll
    for (int i = 0; i < 8; i++) {
        int idx = tid + i*256;
        float val = xp[idx];
        if (rp) val += rp[idx];
        v[i] = val; ss += val*val;
    }
    __shared__ float sh[256];
    sh[tid] = ss; __syncthreads();
    for (int s = 128; s > 0; s >>= 1) { if (tid < s) sh[tid] += sh[tid+s]; __syncthreads(); }
    float scale = rsqrtf(sh[0]/(float)kH + kEPS);
    #pragma unroll
    for (int i = 0; i < 8; i++) {
        int idx = tid + i*256;
        if (res_out) res_out[(size_t)t*kH + idx] = v[i];
        float hv = v[i]*scale*w[idx];
        h_out[(size_t)t*kH + idx] = rtf(hv);
        if (h_full) h_full[(size_t)t*kH + idx] = hv;
    }
}

// fused: h = p0 + p1 + res_in; res = h; h2 = rtf(rms); h2f = rms  (ln2 path, absorbs o-proj reduce)
__global__ void add_rms3_kernel(const float* __restrict__ p0,const float* __restrict__ p1,
                                const float* __restrict__ w,float* __restrict__ res_io,
                                float* __restrict__ h_out,float* __restrict__ h_full){
    const int t = blockIdx.x, tid = threadIdx.x;
    float v[8]; float ss = 0.f;
    #pragma unroll
    for (int i = 0; i < 8; i++) {
        int idx = tid + i*256;
        size_t o = (size_t)t*kH + idx;
        float val = p0[o] + p1[o] + res_io[o];   // same order as reduce(p0+p1)+res
        v[i] = val; ss += val*val;
    }
    __shared__ float sh[256];
    sh[tid] = ss; __syncthreads();
    for (int s = 128; s > 0; s >>= 1) { if (tid < s) sh[tid] += sh[tid+s]; __syncthreads(); }
    float scale = rsqrtf(sh[0]/(float)kH + kEPS);
    #pragma unroll
    for (int i = 0; i < 8; i++) {
        int idx = tid + i*256;
        size_t o = (size_t)t*kH + idx;
        res_io[o] = v[i];
        float hv = v[i]*scale*w[idx];
        h_out[o] = rtf(hv);
        if (h_full) h_full[o] = hv;
    }
}

// ---------------- split-K 128x128 GEMM, 256 threads (R11 config) ----------------
__global__ void __launch_bounds__(256, 2)
gemm_splitk_kernel(const float* __restrict__ A,int lda,const float* __restrict__ B,int ldb,
                   float* __restrict__ Cpart,int ldc,int Kdim){
    extern __shared__ unsigned smem[];
    unsigned* As = smem;
    unsigned* Bs = smem + kStages*kABuf;
    const int row0 = blockIdx.x*128, col0 = blockIdx.y*128;
    const int kz = blockIdx.z;
    const int Khalf = Kdim >> 1;
    const int koff = kz*Khalf;
    const int tid = threadIdx.x, lane = tid&31, warp = tid>>5;
    const int wm = (warp&1)*64, wn = (warp>>1)*32;
    const int g = lane>>2, t = lane&3;
    const float* Ab = A + (size_t)row0*lda + koff;
    const float* Bb = B + (size_t)koff*ldb + col0;
    float* C = Cpart + (size_t)kz*kT*ldc;
    const int nk = Khalf >> 5;

    auto issue = [&](int s){
        unsigned* Ad = As + (s%kStages)*kABuf;
        unsigned* Bd = Bs + (s%kStages)*kBBuf;
        int kk0 = s*32;
        #pragma unroll
        for (int q = 0; q < 4; q++) {
            int e = tid + q*256;
            int m = e>>3, k4 = e&7;
            cp16(sptr(Ad + m*kSA + k4*4), Ab + (size_t)m*lda + kk0 + k4*4);
        }
        #pragma unroll
        for (int q = 0; q < 4; q++) {
            int e = tid + q*256;
            int k = e>>5, n16 = e&31;
            cp16(sptr(Bd + k*kSB + n16*4), Bb + (size_t)(kk0+k)*ldb + n16*4);
        }
        cp_commit();
    };
    for (int s = 0; s < kStages-1; s++) { if (s < nk) issue(s); else cp_commit(); }

    const unsigned aO = a_off(wm,lane);
    float acc[4][4][4] = {};
    for (int i = 0; i < nk; i++) {
        cp_wait1();
        __syncthreads();
        int s = i + kStages - 1;
        if (s < nk) issue(s); else cp_commit();
        compute_plain<true>(sptr(As + (i%kStages)*kABuf) + aO, Bs + (i%kStages)*kBBuf, wn, g, t, acc);
    }
    #pragma unroll
    for (int im = 0; im < 4; im++)
        #pragma unroll
        for (int jn = 0; jn < 4; jn++) {
            int r0 = row0 + wm + im*16 + g;
            int c0 = col0 + wn + jn*8 + 2*t;
            #pragma unroll
            for (int hh = 0; hh < 2; hh++) {
                int rr = r0 + hh*8;
                C[(size_t)rr*ldc + c0]   = acc[im][jn][hh*2+0];
                C[(size_t)rr*ldc + c0+1] = acc[im][jn][hh*2+1];
            }
        }
}

// ---------------- QK-RMSNorm + RoPE; reads split-K partials directly ----------------
__global__ void rope_kernel(const int* __restrict__ positions,const float* __restrict__ q_norm_w,
                            const float* __restrict__ k_norm_w){
    const int t = blockIdx.x, hh = blockIdx.y, lane = threadIdx.x;
    const float* p0 = g_part;
    const float* p1 = g_part + (size_t)kT*kQKV;
    if (hh >= kNH + kNKV) {
        int vh = hh - kNH - kNKV;
        size_t o = (size_t)t*kQKV + (kNH+kNKV)*kHD + vh*kHD + lane;
        g_qkv[o] = rtf(p0[o] + p1[o]);
        return;
    }
    const size_t base = (size_t)t*kQKV + (hh < kNH ? hh*kHD : kNH*kHD + (hh-kNH)*kHD);
    const float* nw = (hh < kNH) ? q_norm_w : k_norm_w;
    float v = p0[base + lane] + p1[base + lane];
    __shared__ float sred[128];
    sred[lane] = v*v; __syncthreads();
    for (int s = 64; s > 0; s >>= 1) { if (lane < s) sred[lane] += sred[lane+s]; __syncthreads(); }
    float scale = rsqrtf(sred[0]/(float)kHD + kEPS);
    float xn = v*scale*nw[lane];
    __shared__ float sh[128];
    sh[lane] = xn; __syncthreads();
    int j = lane & 63;
    const float kLog2Theta_64 = 19.931568569324174f / 64.0f;
    float inv = exp2f(-(float)j * kLog2Theta_64);
    float ang = (float)positions[t] * inv;
    float s, c;
    sincosf(ang, &s, &c);
    float outv = (lane < 64) ? sh[lane]*c - sh[lane+64]*s : sh[lane]*c + sh[lane-64]*s;
    g_qkv[base + lane] = rtf(outv);
}

__global__ void __launch_bounds__(256,2) scores_kernel(){
    const int qt = blockIdx.x, kt = blockIdx.y, h = blockIdx.z;
    if (kt > qt) return;
    extern __shared__ unsigned smw[];
    unsigned* As = smw;
    unsigned* Bst = smw + kStages*kABuf;
    const float* Q  = g_qkv + (size_t)qt*128*kQKV + h*kHD;
    const float* Kp = g_qkv + (size_t)kt*128*kQKV + kNH*kHD + (h>>2)*kHD;
    const int tid = threadIdx.x, lane = tid&31, warp = tid>>5;
    const int wm = (warp&1)*64, wn = (warp>>1)*32;
    const int g = lane>>2, t = lane&3;
    const int nk = kHD >> 5;
    auto issue = [&](int s){
        unsigned* Ad = As + (s%kStages)*kABuf;
        unsigned* Bd = Bst + (s%kStages)*kABuf;
        int kk0 = s*32;
        #pragma unroll
        for (int q = 0; q < 4; q++) {
            int e = tid + q*256;
            int m = e>>3, k4 = e&7;
            cp16(sptr(Ad + m*kSA + k4*4), Q  + (size_t)m*kQKV + kk0 + k4*4);
            cp16(sptr(Bd + m*kSA + k4*4), Kp + (size_t)m*kQKV + kk0 + k4*4);
        }
        cp_commit();
    };
    for (int s = 0; s < kStages-1; s++) { if (s < nk) issue(s); else cp_commit(); }
    const unsigned aO = a_off(wm,lane), b0 = b_off(wn,0,lane), b1 = b_off(wn,1,lane);
    float acc[4][4][4] = {};
    for (int i = 0; i < nk; i++) {
        cp_wait1();
        __syncthreads();
        int s = i + kStages - 1;
        if (s < nk) issue(s); else cp_commit();
        int p = i % kStages;
        compute_tt(sptr(As+p*kABuf)+aO, sptr(Bst+p*kABuf)+b0, sptr(Bst+p*kABuf)+b1, acc);
    }
    const int row0 = qt*128, col0 = kt*128;
    #pragma unroll
    for (int im = 0; im < 4; im++)
        #pragma unroll
        for (int jn = 0; jn < 4; jn++) {
            int r0 = row0 + wm + im*16 + g;
            int c0 = col0 + wn + jn*8 + 2*t;
            #pragma unroll
            for (int hh = 0; hh < 2; hh++) {
                int qi = r0 + hh*8;
                float v0 = acc[im][jn][hh*2+0]*kScale;
                float v1 = acc[im][jn][hh*2+1]*kScale;
                if (c0   > qi) v0 = -1e9f;
                if (c0+1 > qi) v1 = -1e9f;
                g_scores[((size_t)h*kT+qi)*kT + c0]   = v0;
                g_scores[((size_t)h*kT+qi)*kT + c0+1] = v1;
            }
        }
}

__global__ void softmax_kernel(){
    const int q = blockIdx.x, h = blockIdx.y, tid = threadIdx.x;
    float* row = g_scores + ((size_t)h*kT + q)*kT;
    const int tend = ((q>>7)+1)<<7;
    __shared__ float sh[256];
    float lmax = -3.4e38f;
    for (int k = tid; k <= q; k += 256) lmax = fmaxf(lmax, row[k]);
    sh[tid] = lmax; __syncthreads();
    for (int s = 128; s > 0; s >>= 1) { if (tid < s) sh[tid] = fmaxf(sh[tid], sh[tid+s]); __syncthreads(); }
    float m = sh[0]; __syncthreads();
    float lsum = 0.f;
    for (int k = tid; k <= q; k += 256) { float e = __expf(row[k]-m); row[k] = e; lsum += e; }
    sh[tid] = lsum; __syncthreads();
    for (int s = 128; s > 0; s >>= 1) { if (tid < s) sh[tid] += sh[tid+s]; __syncthreads(); }
    float inv = 1.f/sh[0];
    for (int k = tid; k < tend; k += 256) row[k] = (k <= q) ? rtf(row[k]*inv) : 0.f;
}

__global__ void __launch_bounds__(256,2) pv_kernel(){
    const int qt = blockIdx.x, h = blockIdx.y;
    extern __shared__ unsigned smw[];
    unsigned* As = smw;
    unsigned* Bs = smw + kStages*kABuf;
    const int row0 = qt*128;
    const int Kdim = (qt+1)*128;
    const float* A = g_scores + ((size_t)h*kT + row0)*kT;
    const float* B = g_qkv + (kNH+kNKV)*kHD + (h>>2)*kHD;
    const int tid = threadIdx.x, lane = tid&31, warp = tid>>5;
    const int wm = (warp&1)*64, wn = (warp>>1)*32;
    const int g = lane>>2, t = lane&3;
    const int nk = Kdim >> 5;
    auto issue = [&](int s){
        unsigned* Ad = As + (s%kStages)*kABuf;
        unsigned* Bd = Bs + (s%kStages)*kBBuf;
        int kk0 = s*32;
        #pragma unroll
        for (int q = 0; q < 4; q++) {
            int e = tid + q*256;
            int m = e>>3, k4 = e&7;
            cp16(sptr(Ad + m*kSA + k4*4), A + (size_t)m*kT + kk0 + k4*4);
        }
        #pragma unroll
        for (int q = 0; q < 4; q++) {
            int e = tid + q*256;
            int k = e>>5, n16 = e&31;
            cp16(sptr(Bd + k*kSB + n16*4), B + (size_t)(kk0+k)*kQKV + n16*4);
        }
        cp_commit();
    };
    for (int s = 0; s < kStages-1; s++) { if (s < nk) issue(s); else cp_commit(); }
    const unsigned aO = a_off(wm,lane);
    float acc[4][4][4] = {};
    for (int i = 0; i < nk; i++) {
        cp_wait1();
        __syncthreads();
        int s = i + kStages - 1;
        if (s < nk) issue(s); else cp_commit();
        int p = i % kStages;
        compute_plain<false>(sptr(As+p*kABuf)+aO, Bs+p*kBBuf, wn, g, t, acc);
    }
    #pragma unroll
    for (int im = 0; im < 4; im++)
        #pragma unroll
        for (int jn = 0; jn < 4; jn++) {
            int r0 = row0 + wm + im*16 + g;
            int c0 = wn + jn*8 + 2*t;
            #pragma unroll
            for (int hh = 0; hh < 2; hh++) {
                int rr = r0 + hh*8;
                g_attn[(size_t)rr*kH + h*kHD + c0]   = rtf(acc[im][jn][hh*2+0]);
                g_attn[(size_t)rr*kH + h*kHD + c0+1] = rtf(acc[im][jn][hh*2+1]);
            }
        }
}

__global__ void router_kernel(const float* __restrict__ gate_w){
    const int t = blockIdx.x, tid = threadIdx.x;
    const float* hp = g_h2f + (size_t)t*kH;
    float acc[kE] = {};
    for (int k = tid; k < kH; k += 256) {
        float hv = hp[k];
        const float* gw = gate_w + (size_t)k*kE;
        #pragma unroll
        for (int e = 0; e < kE; e++) acc[e] += hv*gw[e];
    }
    __shared__ float sh[kE][256];
    #pragma unroll
    for (int e = 0; e < kE; e++) sh[e][tid] = acc[e];
    __syncthreads();
    for (int s = 128; s > 0; s >>= 1) {
        if (tid < s) {
            #pragma unroll
            for (int e = 0; e < kE; e++) sh[e][tid] += sh[e][tid+s];
        }
        __syncthreads();
    }
    if (tid == 0) {
        float l[kE], mx = -3.4e38f;
        #pragma unroll
        for (int e = 0; e < kE; e++) { l[e] = sh[e][0]; mx = fmaxf(mx, l[e]); }
        float sum = 0.f;
        #pragma unroll
        for (int e = 0; e < kE; e++) { l[e] = __expf(l[e]-mx); sum += l[e]; }
        float isum = 1.f/sum;
        float best = -1.f, second = -1.f; int bi = 0, si = 0;
        #pragma unroll
        for (int e = 0; e < kE; e++) {
            float p = l[e]*isum;
            if (p > best) { second = best; si = bi; best = p; bi = e; }
            else if (p > second) { second = p; si = e; }
        }
        float denom = 1.f/(best + second);
        g_topi[t*2]   = bi; g_topw[t*2]   = best*denom;
        g_topi[t*2+1] = si; g_topw[t*2+1] = second*denom;
        atomicAdd(&g_cnt[bi], 1);
        atomicAdd(&g_cnt[si], 1);
    }
}

__global__ void moe_init_kernel(){
    int i = blockIdx.x*256 + threadIdx.x;
    if (i < kE) g_cnt[i] = 0;
    if (i < kSlots) g_tok[i] = kT;
    if (i < kH) g_h2[(size_t)kT*kH + i] = 0.f;
}
__global__ void moe_setup_kernel(){
    int off = 0, tile = 0;
    for (int e = 0; e < kE; e++) {
        g_cursor[e] = off;
        int seg = ((g_cnt[e] + 127)/128)*128;
        for (int i = 0; i < seg/128; i++) g_tile_e[tile++] = e;
        off += seg;
    }
    g_ntiles = tile;
}
__global__ void moe_scatter_kernel(){
    int t = blockIdx.x*256 + threadIdx.x;
    if (t >= kT) return;
    #pragma unroll
    for (int k = 0; k < 2; k++) {
        int e = g_topi[t*2+k];
        int pos = atomicAdd(&g_cursor[e], 1);
        g_tok[pos] = t;
        g_wt[pos]  = g_topw[t*2+k];
        g_slot_of[t*2+k] = pos;
    }
}

__global__ void __launch_bounds__(256,2) moe_gu_kernel(const float* __restrict__ w_gate_up){
    const int tile = blockIdx.x;
    if (tile >= g_ntiles) return;
    extern __shared__ unsigned smw[];
    unsigned* As = smw;
    unsigned* Bs = smw + kStages*kABuf;
    __shared__ int rows[128];
    const int tid = threadIdx.x;
    if (tid < 128) rows[tid] = g_tok[tile*128 + tid];
    __syncthreads();
    const int e = g_tile_e[tile];
    const int col0 = blockIdx.y*128;
    const float* Bb = w_gate_up + (size_t)e*kH*2*kI + col0;
    const int lane = tid&31, warp = tid>>5;
    const int wm = (warp&1)*64, wn = (warp>>1)*32;
    const int g = lane>>2, t = lane&3;
    const int nk = kH >> 5;
    auto issue = [&](int s){
        unsigned* Ad = As + (s%kStages)*kABuf;
        unsigned* Bd = Bs + (s%kStages)*kBBuf;
        int kk0 = s*32;
        #pragma unroll
        for (int q = 0; q < 4; q++) {
            int ee = tid + q*256;
            int m = ee>>3, k4 = ee&7;
            cp16(sptr(Ad + m*kSA + k4*4), g_h2 + (size_t)rows[m]*kH + kk0 + k4*4);
        }
        #pragma unroll
        for (int q = 0; q < 4; q++) {
            int ee = tid + q*256;
            int k = ee>>5, n16 = ee&31;
            cp16(sptr(Bd + k*kSB + n16*4), Bb + (size_t)(kk0+k)*(2*kI) + n16*4);
        }
        cp_commit();
    };
    for (int s = 0; s < kStages-1; s++) { if (s < nk) issue(s); else cp_commit(); }
    const unsigned aO = a_off(wm,lane);
    float acc[4][4][4] = {};
    for (int i = 0; i < nk; i++) {
        cp_wait1();
        __syncthreads();
        int s = i + kStages - 1;
        if (s < nk) issue(s); else cp_commit();
        int p = i % kStages;
        compute_plain<true>(sptr(As+p*kABuf)+aO, Bs+p*kBBuf, wn, g, t, acc);
    }
    #pragma unroll
    for (int im = 0; im < 4; im++)
        #pragma unroll
        for (int jn = 0; jn < 4; jn++) {
            int r0 = wm + im*16 + g;
            int c0 = col0 + wn + jn*8 + 2*t;
            #pragma unroll
            for (int hh = 0; hh < 2; hh++) {
                int slot = tile*128 + r0 + hh*8;
                g_gu[(size_t)slot*2*kI + c0]   = acc[im][jn][hh*2+0];
                g_gu[(size_t)slot*2*kI + c0+1] = acc[im][jn][hh*2+1];
            }
        }
}

__global__ void silu_kernel(){
    int idx = blockIdx.x*256 + threadIdx.x;
    int slot = idx / kI, j = idx % kI;
    if (slot >= g_ntiles*128) return;
    float g = g_gu[(size_t)slot*2*kI + j];
    float u = g_gu[(size_t)slot*2*kI + kI + j];
    g_act[idx] = rtf((g / (1.f + __expf(-g))) * u);
}

__global__ void __launch_bounds__(256,2) moe_down_kernel(const float* __restrict__ w_down){
    const int tile = blockIdx.x;
    if (tile >= g_ntiles) return;
    extern __shared__ unsigned smw[];
    unsigned* As = smw;
    unsigned* Bs = smw + kStages*kABuf;
    const int e = g_tile_e[tile];
    const int col0 = blockIdx.y*128;
    const float* A  = g_act + (size_t)tile*128*kI;
    const float* Bb = w_down + (size_t)e*kI*kH + col0;
    const int tid = threadIdx.x, lane = tid&31, warp = tid>>5;
    const int wm = (warp&1)*64, wn = (warp>>1)*32;
    const int g = lane>>2, t = lane&3;
    const int nk = kI >> 5;
    auto issue = [&](int s){
        unsigned* Ad = As + (s%kStages)*kABuf;
        unsigned* Bd = Bs + (s%kStages)*kBBuf;
        int kk0 = s*32;
        #pragma unroll
        for (int q = 0; q < 4; q++) {
            int ee = tid + q*256;
            int m = ee>>3, k4 = ee&7;
            cp16(sptr(Ad + m*kSA + k4*4), A + (size_t)m*kI + kk0 + k4*4);
        }
        #pragma unroll
        for (int q = 0; q < 4; q++) {
            int ee = tid + q*256;
            int k = ee>>5, n16 = ee&31;
            cp16(sptr(Bd + k*kSB + n16*4), Bb + (size_t)(kk0+k)*kH + n16*4);
        }
        cp_commit();
    };
    for (int s = 0; s < kStages-1; s++) { if (s < nk) issue(s); else cp_commit(); }
    const unsigned aO = a_off(wm,lane);
    float acc[4][4][4] = {};
    for (int i = 0; i < nk; i++) {
        cp_wait1();
        __syncthreads();
        int s = i + kStages - 1;
        if (s < nk) issue(s); else cp_commit();
        int p = i % kStages;
        compute_plain<true>(sptr(As+p*kABuf)+aO, Bs+p*kBBuf, wn, g, t, acc);
    }
    #pragma unroll
    for (int im = 0; im < 4; im++)
        #pragma unroll
        for (int jn = 0; jn < 4; jn++) {
            int r0 = wm + im*16 + g;
            int c0 = col0 + wn + jn*8 + 2*t;
            #pragma unroll
            for (int hh = 0; hh < 2; hh++) {
                int slot = tile*128 + r0 + hh*8;
                g_ds[(size_t)slot*kH + c0]   = acc[im][jn][hh*2+0];
                g_ds[(size_t)slot*kH + c0+1] = acc[im][jn][hh*2+1];
            }
        }
}

__global__ void combine_kernel(float* __restrict__ out){
    const int t = blockIdx.x;
    const int s0 = g_slot_of[t*2], s1 = g_slot_of[t*2+1];
    const float w0 = g_wt[s0], w1 = g_wt[s1];
    for (int j = threadIdx.x; j < kH; j += 256)
        out[(size_t)t*kH + j] = w0*g_ds[(size_t)s0*kH + j] + w1*g_ds[(size_t)s1*kH + j];
}

extern "C" void kernel_launch(void* const* d_in, const int* in_sizes, int n_in,
                              void* d_out, int out_size) {
    const int*   positions = (const int*)  d_in[0];
    const float* hidden    = (const float*)d_in[1];
    const float* residual  = (const float*)d_in[2];
    const float* w_qkv     = (const float*)d_in[3];
    const float* w_o       = (const float*)d_in[4];
    const float* q_norm_w  = (const float*)d_in[5];
    const float* k_norm_w  = (const float*)d_in[6];
    const float* ln1_w     = (const float*)d_in[7];
    const float* ln2_w     = (const float*)d_in[8];
    const float* gate_w    = (const float*)d_in[9];
    const float* w_gate_up = (const float*)d_in[10];
    const float* w_down    = (const float*)d_in[11];
    float* out = (float*)d_out;
    float* res = out + (size_t)kT*kH;

    float* d_h1;   cudaGetSymbolAddress((void**)&d_h1,  g_h1);
    float* d_part; cudaGetSymbolAddress((void**)&d_part,g_part);
    float* d_attn; cudaGetSymbolAddress((void**)&d_attn,g_attn);
    float* d_h2;   cudaGetSymbolAddress((void**)&d_h2,  g_h2);
    float* d_h2f;  cudaGetSymbolAddress((void**)&d_h2f, g_h2f);

    cudaFuncSetAttribute(gemm_splitk_kernel, cudaFuncAttributeMaxDynamicSharedMemorySize, (int)kPlainSmem);
    cudaFuncSetAttribute(scores_kernel,      cudaFuncAttributeMaxDynamicSharedMemorySize, (int)kTTSmem);
    cudaFuncSetAttribute(pv_kernel,          cudaFuncAttributeMaxDynamicSharedMemorySize, (int)kPlainSmem);
    cudaFuncSetAttribute(moe_gu_kernel,      cudaFuncAttributeMaxDynamicSharedMemorySize, (int)kPlainSmem);
    cudaFuncSetAttribute(moe_down_kernel,    cudaFuncAttributeMaxDynamicSharedMemorySize, (int)kPlainSmem);

    add_rms_kernel<<<kT, 256>>>(hidden, residual, ln1_w, res, d_h1, nullptr);
    gemm_splitk_kernel<<<dim3(kT/128, kQKV/128, 2), 256, kPlainSmem>>>(d_h1, kH, w_qkv, kQKV, d_part, kQKV, kH);
    rope_kernel<<<dim3(kT, kNH + 2*kNKV), 128>>>(positions, q_norm_w, k_norm_w);  // fuses QKV reduce
    scores_kernel<<<dim3(kT/128, kT/128, kNH), 256, kTTSmem>>>();
    softmax_kernel<<<dim3(kT, kNH), 256>>>();
    pv_kernel<<<dim3(kT/128, kNH), 256, kPlainSmem>>>();
    gemm_splitk_kernel<<<dim3(kT/128, kH/128, 2), 256, kPlainSmem>>>(d_attn, kH, w_o, kH, d_part, kH, kH);
    add_rms3_kernel<<<kT, 256>>>(d_part, d_part + (size_t)kT*kH, ln2_w, res, d_h2, d_h2f);  // fuses o-proj reduce
    moe_init_kernel<<<(kSlots + 255)/256, 256>>>();
    router_kernel<<<kT, 256>>>(gate_w);
    moe_setup_kernel<<<1, 1>>>();
    moe_scatter_kernel<<<(kT + 255)/256, 256>>>();
    moe_gu_kernel<<<dim3(kTiles, 2*kI/128), 256, kPlainSmem>>>(w_gate_up);
    silu_kernel<<<(kSlots*kI)/256, 256>>>();
    moe_down_kernel<<<dim3(kTiles, kH/128), 256, kPlainSmem>>>(w_down);
    combine_kernel<<<kT, 256>>>(out);
}